// round 1
// baseline (speedup 1.0000x reference)
#include <cuda_runtime.h>
#include <math.h>

#define B_ 32
#define S_ 2048
#define H_ 1024
#define D_ 2048   // H * L

// ---- scratch (no allocations allowed) ----
__device__ float g_qproj[B_ * H_];          // q@Wa + Wa_b + Ua_b, [B,H]
__device__ float g_spart[8 * B_ * S_];      // partial scores per h-block (1024/128 = 8)

// ============================================================
// K1: q projection. grid (H/256, B/4), block 256.
// Each thread: one h column, 4 batches (amortize Wa loads).
// ============================================================
__global__ __launch_bounds__(256) void qproj_kernel(
    const float* __restrict__ query, const float* __restrict__ Wa,
    const float* __restrict__ Wab,   const float* __restrict__ Uab)
{
    int h  = blockIdx.x * 256 + threadIdx.x;
    int b0 = blockIdx.y * 4;
    const float* q0 = query + (size_t)(b0 + 0) * D_;
    const float* q1 = query + (size_t)(b0 + 1) * D_;
    const float* q2 = query + (size_t)(b0 + 2) * D_;
    const float* q3 = query + (size_t)(b0 + 3) * D_;
    float a0 = 0.f, a1 = 0.f, a2 = 0.f, a3 = 0.f;
    #pragma unroll 4
    for (int d = 0; d < D_; d++) {
        float w = Wa[(size_t)d * H_ + h];
        a0 = fmaf(q0[d], w, a0);
        a1 = fmaf(q1[d], w, a1);
        a2 = fmaf(q2[d], w, a2);
        a3 = fmaf(q3[d], w, a3);
    }
    float bias = Wab[h] + Uab[h];   // fold both biases (Va_b cancels in softmax)
    g_qproj[(size_t)(b0 + 0) * H_ + h] = a0 + bias;
    g_qproj[(size_t)(b0 + 1) * H_ + h] = a1 + bias;
    g_qproj[(size_t)(b0 + 2) * H_ + h] = a2 + bias;
    g_qproj[(size_t)(b0 + 3) * H_ + h] = a3 + bias;
}

// ============================================================
// K2: fused keys@Ua -> tanh(q+k)*Va -> partial score.
// Tile: BM=64 (s) x BN=128 (h), BK=16; 256 threads, 4x8 microtile.
// grid (S/64, H/128, B).  Partial over its 128-h slab is written
// (not accumulated) to g_spart[blockIdx.y][b][s] -> deterministic.
// ============================================================
#define BM 64
#define BN 128
#define BK 16
#define TM 4
#define TN 8

__global__ __launch_bounds__(256) void score_kernel(
    const float* __restrict__ keys, const float* __restrict__ Ua,
    const float* __restrict__ Va)
{
    __shared__ float As[BK][BM];        // keys tile, transposed
    __shared__ float Bs[BK][BN];        // Ua tile
    __shared__ float red[BM][17];       // epilogue reduction

    const int b  = blockIdx.z;
    const int s0 = blockIdx.x * BM;
    const int h0 = blockIdx.y * BN;
    const int tid = threadIdx.x;
    const int tx = tid & 15;            // 16 col-groups
    const int ty = tid >> 4;            // 16 row-groups

    const float* kb = keys + (size_t)b * S_ * H_;

    float acc[TM][TN];
    #pragma unroll
    for (int i = 0; i < TM; i++)
        #pragma unroll
        for (int j = 0; j < TN; j++) acc[i][j] = 0.f;

    const int ar = tid >> 2;            // 0..63
    const int ac = (tid & 3) << 2;      // 0,4,8,12

    for (int d0 = 0; d0 < H_; d0 += BK) {
        // load A tile (64x16) as float4, transpose into As[k][m]
        float4 av = *(const float4*)(kb + (size_t)(s0 + ar) * H_ + d0 + ac);
        As[ac + 0][ar] = av.x;
        As[ac + 1][ar] = av.y;
        As[ac + 2][ar] = av.z;
        As[ac + 3][ar] = av.w;
        // load B tile (16x128): 2 float4 per thread, coalesced
        #pragma unroll
        for (int i = 0; i < 2; i++) {
            int idx = tid + i * 256;
            int br = idx >> 5;              // 0..15
            int bc = (idx & 31) << 2;       // 0..124
            *(float4*)&Bs[br][bc] =
                *(const float4*)(Ua + (size_t)(d0 + br) * H_ + h0 + bc);
        }
        __syncthreads();

        #pragma unroll
        for (int kk = 0; kk < BK; kk++) {
            float a[TM];
            #pragma unroll
            for (int i = 0; i < TM; i++) a[i] = As[kk][ty * TM + i];
            float4 bv0 = *(const float4*)&Bs[kk][tx * TN];
            float4 bv1 = *(const float4*)&Bs[kk][tx * TN + 4];
            float bb[TN] = {bv0.x, bv0.y, bv0.z, bv0.w, bv1.x, bv1.y, bv1.z, bv1.w};
            #pragma unroll
            for (int i = 0; i < TM; i++)
                #pragma unroll
                for (int j = 0; j < TN; j++)
                    acc[i][j] = fmaf(a[i], bb[j], acc[i][j]);
        }
        __syncthreads();
    }

    // epilogue: p[i] = sum_j tanh(acc + qproj) * Va
    float p[TM] = {0.f, 0.f, 0.f, 0.f};
    #pragma unroll
    for (int j = 0; j < TN; j++) {
        int h = h0 + tx * TN + j;
        float va = Va[h];
        float qh = g_qproj[(size_t)b * H_ + h];
        #pragma unroll
        for (int i = 0; i < TM; i++)
            p[i] += tanhf(acc[i][j] + qh) * va;
    }
    #pragma unroll
    for (int i = 0; i < TM; i++) red[ty * TM + i][tx] = p[i];
    __syncthreads();

    if (tid < BM) {
        float s = 0.f;
        #pragma unroll
        for (int j = 0; j < 16; j++) s += red[tid][j];
        g_spart[(size_t)blockIdx.y * (B_ * S_) + (size_t)b * S_ + s0 + tid] = s;
    }
}

// ============================================================
// K3: softmax over S per batch. grid B, block 256 (8 s per thread).
// Sums the 8 h-block partials, then max/exp/sum/normalize.
// ============================================================
__global__ __launch_bounds__(256) void softmax_kernel(float* __restrict__ weights)
{
    const int b = blockIdx.x;
    const int tid = threadIdx.x;
    const int lane = tid & 31, wid = tid >> 5;
    __shared__ float sred[8];

    float v[8];
    #pragma unroll
    for (int i = 0; i < 8; i++) {
        int s = tid + i * 256;
        float t = 0.f;
        #pragma unroll
        for (int hb = 0; hb < 8; hb++)
            t += g_spart[(size_t)hb * (B_ * S_) + (size_t)b * S_ + s];
        v[i] = t;
    }
    // max
    float m = v[0];
    #pragma unroll
    for (int i = 1; i < 8; i++) m = fmaxf(m, v[i]);
    #pragma unroll
    for (int off = 16; off > 0; off >>= 1)
        m = fmaxf(m, __shfl_xor_sync(0xFFFFFFFFu, m, off));
    if (lane == 0) sred[wid] = m;
    __syncthreads();
    float mm = sred[0];
    #pragma unroll
    for (int w = 1; w < 8; w++) mm = fmaxf(mm, sred[w]);
    __syncthreads();
    // exp + sum
    float sum = 0.f;
    #pragma unroll
    for (int i = 0; i < 8; i++) { v[i] = __expf(v[i] - mm); sum += v[i]; }
    #pragma unroll
    for (int off = 16; off > 0; off >>= 1)
        sum += __shfl_xor_sync(0xFFFFFFFFu, sum, off);
    if (lane == 0) sred[wid] = sum;
    __syncthreads();
    float tot = 0.f;
    #pragma unroll
    for (int w = 0; w < 8; w++) tot += sred[w];
    float inv = 1.0f / tot;
    #pragma unroll
    for (int i = 0; i < 8; i++)
        weights[(size_t)b * S_ + tid + i * 256] = v[i] * inv;
}

// ============================================================
// K4: context[b,h] = sum_s w[b,s]*keys[b,s,h]. grid (H/256, B).
// Weights staged in smem; coalesced streaming of keys (HBM-bound).
// ============================================================
__global__ __launch_bounds__(256) void context_kernel(
    const float* __restrict__ keys, const float* __restrict__ weights,
    float* __restrict__ ctx)
{
    const int b = blockIdx.y;
    const int h = blockIdx.x * 256 + threadIdx.x;
    __shared__ float sw[S_];
    #pragma unroll
    for (int i = 0; i < 8; i++)
        sw[threadIdx.x + i * 256] = weights[(size_t)b * S_ + threadIdx.x + i * 256];
    __syncthreads();

    const float* kb = keys + (size_t)b * S_ * H_ + h;
    float a0 = 0.f, a1 = 0.f, a2 = 0.f, a3 = 0.f;
    for (int s = 0; s < S_; s += 4) {
        a0 = fmaf(sw[s + 0], kb[(size_t)(s + 0) * H_], a0);
        a1 = fmaf(sw[s + 1], kb[(size_t)(s + 1) * H_], a1);
        a2 = fmaf(sw[s + 2], kb[(size_t)(s + 2) * H_], a2);
        a3 = fmaf(sw[s + 3], kb[(size_t)(s + 3) * H_], a3);
    }
    ctx[(size_t)b * H_ + h] = (a0 + a1) + (a2 + a3);
}

// ============================================================
extern "C" void kernel_launch(void* const* d_in, const int* in_sizes, int n_in,
                              void* d_out, int out_size)
{
    const float* query = (const float*)d_in[0];
    const float* keys  = (const float*)d_in[1];
    const float* Wa_w  = (const float*)d_in[2];
    const float* Wa_b  = (const float*)d_in[3];
    const float* Ua_w  = (const float*)d_in[4];
    const float* Ua_b  = (const float*)d_in[5];
    const float* Va_w  = (const float*)d_in[6];
    // d_in[7] = Va_b: constant shift of scores -> cancels in softmax; unused.

    float* ctx = (float*)d_out;                 // [B,1,H] first
    float* wts = (float*)d_out + B_ * H_;       // [B,1,S] second

    qproj_kernel<<<dim3(H_ / 256, B_ / 4), 256>>>(query, Wa_w, Wa_b, Ua_b);
    score_kernel<<<dim3(S_ / BM, H_ / BN, B_), 256>>>(keys, Ua_w, Va_w);
    softmax_kernel<<<B_, 256>>>(wts);
    context_kernel<<<dim3(H_ / 256, B_), 256>>>(keys, wts, ctx);
}

// round 3
// speedup vs baseline: 3.0243x; 3.0243x over previous
#include <cuda_runtime.h>
#include <cuda_bf16.h>
#include <math.h>
#include <stdint.h>

#define B_ 32
#define S_ 2048
#define H_ 1024
#define D_ 2048     // H * L
#define MROWS 65536 // B*S

// ---------------- scratch (device globals; no runtime alloc) ----------------
__device__ float g_qproj[B_ * H_];                         // q@Wa + Wa_b + Ua_b
__device__ float g_spart[4 * MROWS];                       // partial scores per 256-h block
__device__ float g_cpart[4 * B_ * H_];                     // context partials
__device__ __align__(128) __nv_bfloat16 g_keys_hi[(size_t)MROWS * H_];  // 128MB
__device__ __align__(128) __nv_bfloat16 g_keys_lo[(size_t)MROWS * H_];  // 128MB
__device__ __align__(128) __nv_bfloat16 g_UaT_hi[H_ * H_]; // Ua^T split hi [h][d]
__device__ __align__(128) __nv_bfloat16 g_UaT_lo[H_ * H_]; // Ua^T split lo [h][d]

// ---------------- PTX helpers (base PTX only: sm_80/90, no 'a' features) ----
__device__ __forceinline__ uint32_t smem_u32(const void* p) {
    uint32_t a;
    asm("{ .reg .u64 t; cvta.to.shared.u64 t, %1; cvt.u32.u64 %0, t; }" : "=r"(a) : "l"(p));
    return a;
}
__device__ __forceinline__ void cpasync16(uint32_t dst, const void* src) {
    asm volatile("cp.async.cg.shared.global [%0], [%1], 16;" :: "r"(dst), "l"(src));
}
#define CP_COMMIT() asm volatile("cp.async.commit_group;" ::: "memory")
#define CP_WAIT2()  asm volatile("cp.async.wait_group 2;" ::: "memory")

__device__ __forceinline__ void ldsm4(uint32_t (&r)[4], uint32_t a) {
    asm volatile("ldmatrix.sync.aligned.m8n8.x4.shared.b16 {%0,%1,%2,%3}, [%4];"
                 : "=r"(r[0]), "=r"(r[1]), "=r"(r[2]), "=r"(r[3]) : "r"(a));
}
__device__ __forceinline__ void mma16816(float (&d)[4], const uint32_t (&a)[4],
                                         uint32_t b0, uint32_t b1) {
    asm volatile(
        "mma.sync.aligned.m16n8k16.row.col.f32.bf16.bf16.f32 "
        "{%0,%1,%2,%3}, {%4,%5,%6,%7}, {%8,%9}, {%0,%1,%2,%3};"
        : "+f"(d[0]), "+f"(d[1]), "+f"(d[2]), "+f"(d[3])
        : "r"(a[0]), "r"(a[1]), "r"(a[2]), "r"(a[3]), "r"(b0), "r"(b1));
}

// pair-line swizzle: rows are 64B (32 bf16); two rows share a 128B line.
// chunk c in 0..3 (16B units). Conflict-free for ldmatrix 8-row groups.
__device__ __forceinline__ uint32_t swb(int r, int c) {
    return (uint32_t)((r >> 1) * 128 + ((((r & 1) << 2) | c) ^ ((r >> 1) & 7)) * 16);
}

__device__ __forceinline__ float tanh_fast(float x) {
    float e = __expf(-2.f * fabsf(x));
    return copysignf(__fdividef(1.f - e, 1.f + e), x);
}

// ============================================================
// P0: keys fp32 -> bf16 hi/lo split. 64M floats.
// ============================================================
__global__ __launch_bounds__(256) void keys_split_kernel(const float* __restrict__ keys)
{
    size_t i = ((size_t)blockIdx.x * 256 + threadIdx.x) * 4;
    float4 v = *(const float4*)(keys + i);
    __nv_bfloat16 hx = __float2bfloat16(v.x), hy = __float2bfloat16(v.y);
    __nv_bfloat16 hz = __float2bfloat16(v.z), hw = __float2bfloat16(v.w);
    __nv_bfloat162 h0 = __nv_bfloat162(hx, hy), h1 = __nv_bfloat162(hz, hw);
    __nv_bfloat162 l0 = __nv_bfloat162(__float2bfloat16(v.x - __bfloat162float(hx)),
                                       __float2bfloat16(v.y - __bfloat162float(hy)));
    __nv_bfloat162 l1 = __nv_bfloat162(__float2bfloat16(v.z - __bfloat162float(hz)),
                                       __float2bfloat16(v.w - __bfloat162float(hw)));
    *(__nv_bfloat162*)(g_keys_hi + i)     = h0;
    *(__nv_bfloat162*)(g_keys_hi + i + 2) = h1;
    *(__nv_bfloat162*)(g_keys_lo + i)     = l0;
    *(__nv_bfloat162*)(g_keys_lo + i + 2) = l1;
}

// ============================================================
// P1: Ua transpose + bf16 hi/lo split.  Ua[d][h] -> UaT[h][d]
// ============================================================
__global__ __launch_bounds__(256) void ua_prep_kernel(const float* __restrict__ Ua)
{
    __shared__ float tile[32][33];
    int tx = threadIdx.x & 31, ty = threadIdx.x >> 5;
    int x0 = blockIdx.x * 32, y0 = blockIdx.y * 32;   // x: h, y: d
    #pragma unroll
    for (int j = 0; j < 4; j++)
        tile[ty + j * 8][tx] = Ua[(size_t)(y0 + ty + j * 8) * H_ + x0 + tx];
    __syncthreads();
    #pragma unroll
    for (int j = 0; j < 4; j++) {
        float v = tile[tx][ty + j * 8];
        __nv_bfloat16 hi = __float2bfloat16(v);
        __nv_bfloat16 lo = __float2bfloat16(v - __bfloat162float(hi));
        size_t o = (size_t)(x0 + ty + j * 8) * H_ + y0 + tx;
        g_UaT_hi[o] = hi;
        g_UaT_lo[o] = lo;
    }
}

// ============================================================
// K1: q projection
// ============================================================
__global__ __launch_bounds__(256) void qproj_kernel(
    const float* __restrict__ query, const float* __restrict__ Wa,
    const float* __restrict__ Wab,   const float* __restrict__ Uab)
{
    int h  = blockIdx.x * 256 + threadIdx.x;
    int b0 = blockIdx.y * 4;
    const float* q0 = query + (size_t)(b0 + 0) * D_;
    const float* q1 = query + (size_t)(b0 + 1) * D_;
    const float* q2 = query + (size_t)(b0 + 2) * D_;
    const float* q3 = query + (size_t)(b0 + 3) * D_;
    float a0 = 0.f, a1 = 0.f, a2 = 0.f, a3 = 0.f;
    #pragma unroll 4
    for (int d = 0; d < D_; d++) {
        float w = Wa[(size_t)d * H_ + h];
        a0 = fmaf(q0[d], w, a0);
        a1 = fmaf(q1[d], w, a1);
        a2 = fmaf(q2[d], w, a2);
        a3 = fmaf(q3[d], w, a3);
    }
    float bias = Wab[h] + Uab[h];
    g_qproj[(size_t)(b0 + 0) * H_ + h] = a0 + bias;
    g_qproj[(size_t)(b0 + 1) * H_ + h] = a1 + bias;
    g_qproj[(size_t)(b0 + 2) * H_ + h] = a2 + bias;
    g_qproj[(size_t)(b0 + 3) * H_ + h] = a3 + bias;
}

// ============================================================
// K2: mma.sync score kernel.
// CTA: M=128 (s) x N=256 (h), BK=32, 3-stage cp.async pipeline.
// 8 warps: wm=wid&3 (32 rows each), wn=wid>>2 (128 cols each).
// D = keys @ UaT^T via 3-term bf16 split; fused tanh*Va epilogue.
// grid (4 hblk, 512 sblk).
// ============================================================
#define STAGE 49152           // Ah 8K | Al 8K | Bh 16K | Bl 16K
#define OFS_AH 0
#define OFS_AL 8192
#define OFS_BH 16384
#define OFS_BL 32768
#define SMEM_SCORE (3 * STAGE + 2048)   // + qs(1K) + vs(1K)

__device__ __forceinline__ void load_stage(uint32_t sbase, int d0, int grow0,
                                           int h0, int tid)
{
    #pragma unroll
    for (int t = 0; t < 12; t++) {
        int id = tid + t * 256;
        if (id < 1024) {                      // A: 2 arrays x 128 rows x 4 chunks
            int arr = id >> 9;
            int a   = id & 511;
            int r = a >> 2, c = a & 3;
            const __nv_bfloat16* g = (arr ? g_keys_lo : g_keys_hi)
                                     + (size_t)(grow0 + r) * H_ + d0 + c * 8;
            cpasync16(sbase + (arr ? OFS_AL : OFS_AH) + swb(r, c), g);
        } else {                              // B: 2 arrays x 256 rows x 4 chunks
            int id2 = id - 1024;
            int arr = id2 >> 10;
            int a   = id2 & 1023;
            int r = a >> 2, c = a & 3;
            const __nv_bfloat16* g = (arr ? g_UaT_lo : g_UaT_hi)
                                     + (size_t)(h0 + r) * H_ + d0 + c * 8;
            cpasync16(sbase + (arr ? OFS_BL : OFS_BH) + swb(r, c), g);
        }
    }
}

__global__ __launch_bounds__(256, 1) void score_kernel(const float* __restrict__ Va)
{
    extern __shared__ char smem[];
    const uint32_t sb = smem_u32(smem);
    const int tid  = threadIdx.x;
    const int wid  = tid >> 5, lane = tid & 31;
    const int wm   = wid & 3,  wn   = wid >> 2;

    const int h0    = blockIdx.x * 256;
    const int grow0 = blockIdx.y * 128;
    const int b     = grow0 >> 11;

    float* qs = (float*)(smem + 3 * STAGE);
    float* vs = qs + 256;
    qs[tid] = g_qproj[(size_t)b * H_ + h0 + tid];
    vs[tid] = Va[h0 + tid];

    float acc[2][16][4];
    #pragma unroll
    for (int i = 0; i < 2; i++)
        #pragma unroll
        for (int j = 0; j < 16; j++)
            #pragma unroll
            for (int q = 0; q < 4; q++) acc[i][j][q] = 0.f;

    // prologue: stages 0, 1
    load_stage(sb + 0 * STAGE, 0,  grow0, h0, tid); CP_COMMIT();
    load_stage(sb + 1 * STAGE, 32, grow0, h0, tid); CP_COMMIT();

    for (int it = 0; it < 32; it++) {
        if (it + 2 < 32)
            load_stage(sb + ((it + 2) % 3) * STAGE, (it + 2) * 32, grow0, h0, tid);
        CP_COMMIT();                       // dummy group at tail keeps wait math fixed
        CP_WAIT2();
        __syncthreads();

        const uint32_t sg = sb + (it % 3) * STAGE;
        #pragma unroll
        for (int ks = 0; ks < 2; ks++) {
            const int c = ks * 2 + (lane >> 4);
            uint32_t ah[2][4], al[2][4];
            #pragma unroll
            for (int ms = 0; ms < 2; ms++) {
                int row = wm * 32 + ms * 16 + (lane & 15);
                ldsm4(ah[ms], sg + OFS_AH + swb(row, c));
                ldsm4(al[ms], sg + OFS_AL + swb(row, c));
            }
            #pragma unroll
            for (int ngp = 0; ngp < 4; ngp++) {
                uint32_t bh[2][4], bl[2][4];
                #pragma unroll
                for (int u = 0; u < 2; u++) {
                    int rowb = wn * 128 + (ngp * 2 + u) * 16 + (lane & 15);
                    ldsm4(bh[u], sg + OFS_BH + swb(rowb, c));
                    ldsm4(bl[u], sg + OFS_BL + swb(rowb, c));
                }
                // split 1: Ah * Bh
                #pragma unroll
                for (int u = 0; u < 2; u++) {
                    int nf = (ngp * 2 + u) * 2;
                    #pragma unroll
                    for (int ms = 0; ms < 2; ms++) {
                        mma16816(acc[ms][nf],     ah[ms], bh[u][0], bh[u][2]);
                        mma16816(acc[ms][nf + 1], ah[ms], bh[u][1], bh[u][3]);
                    }
                }
                // split 2: Ah * Bl
                #pragma unroll
                for (int u = 0; u < 2; u++) {
                    int nf = (ngp * 2 + u) * 2;
                    #pragma unroll
                    for (int ms = 0; ms < 2; ms++) {
                        mma16816(acc[ms][nf],     ah[ms], bl[u][0], bl[u][2]);
                        mma16816(acc[ms][nf + 1], ah[ms], bl[u][1], bl[u][3]);
                    }
                }
                // split 3: Al * Bh
                #pragma unroll
                for (int u = 0; u < 2; u++) {
                    int nf = (ngp * 2 + u) * 2;
                    #pragma unroll
                    for (int ms = 0; ms < 2; ms++) {
                        mma16816(acc[ms][nf],     al[ms], bh[u][0], bh[u][2]);
                        mma16816(acc[ms][nf + 1], al[ms], bh[u][1], bh[u][3]);
                    }
                }
            }
        }
        __syncthreads();
    }

    // ---- epilogue: p[row] = sum_h tanh(acc + q[h]) * Va[h] ----
    float pr[2][2] = {{0.f, 0.f}, {0.f, 0.f}};     // [ms][row-half]
    #pragma unroll
    for (int ms = 0; ms < 2; ms++) {
        #pragma unroll
        for (int nf = 0; nf < 16; nf++) {
            int c0 = wn * 128 + nf * 8 + (lane & 3) * 2;
            float q0v = qs[c0], q1v = qs[c0 + 1];
            float v0v = vs[c0], v1v = vs[c0 + 1];
            pr[ms][0] += tanh_fast(acc[ms][nf][0] + q0v) * v0v
                       + tanh_fast(acc[ms][nf][1] + q1v) * v1v;
            pr[ms][1] += tanh_fast(acc[ms][nf][2] + q0v) * v0v
                       + tanh_fast(acc[ms][nf][3] + q1v) * v1v;
        }
    }
    #pragma unroll
    for (int ms = 0; ms < 2; ms++)
        #pragma unroll
        for (int hf = 0; hf < 2; hf++) {
            pr[ms][hf] += __shfl_xor_sync(0xFFFFFFFFu, pr[ms][hf], 1);
            pr[ms][hf] += __shfl_xor_sync(0xFFFFFFFFu, pr[ms][hf], 2);
        }

    float* red = (float*)smem;    // 2 x 128 floats; stage buffers are dead
    if ((lane & 3) == 0) {
        #pragma unroll
        for (int ms = 0; ms < 2; ms++) {
            int row = wm * 32 + ms * 16 + (lane >> 2);
            red[wn * 128 + row]     = pr[ms][0];
            red[wn * 128 + row + 8] = pr[ms][1];
        }
    }
    __syncthreads();
    if (tid < 128)
        g_spart[(size_t)blockIdx.x * MROWS + grow0 + tid] = red[tid] + red[128 + tid];
}

// ============================================================
// K3: softmax over S per batch (4 h-block partials)
// ============================================================
__global__ __launch_bounds__(256) void softmax_kernel(float* __restrict__ weights)
{
    const int b = blockIdx.x;
    const int tid = threadIdx.x;
    const int lane = tid & 31, wid = tid >> 5;
    __shared__ float sred[8];

    float v[8];
    #pragma unroll
    for (int i = 0; i < 8; i++) {
        int s = tid + i * 256;
        float t = 0.f;
        #pragma unroll
        for (int hb = 0; hb < 4; hb++)
            t += g_spart[(size_t)hb * MROWS + (size_t)b * S_ + s];
        v[i] = t;
    }
    float m = v[0];
    #pragma unroll
    for (int i = 1; i < 8; i++) m = fmaxf(m, v[i]);
    #pragma unroll
    for (int off = 16; off > 0; off >>= 1)
        m = fmaxf(m, __shfl_xor_sync(0xFFFFFFFFu, m, off));
    if (lane == 0) sred[wid] = m;
    __syncthreads();
    float mm = sred[0];
    #pragma unroll
    for (int w = 1; w < 8; w++) mm = fmaxf(mm, sred[w]);
    __syncthreads();
    float sum = 0.f;
    #pragma unroll
    for (int i = 0; i < 8; i++) { v[i] = __expf(v[i] - mm); sum += v[i]; }
    #pragma unroll
    for (int off = 16; off > 0; off >>= 1)
        sum += __shfl_xor_sync(0xFFFFFFFFu, sum, off);
    if (lane == 0) sred[wid] = sum;
    __syncthreads();
    float tot = 0.f;
    #pragma unroll
    for (int w = 0; w < 8; w++) tot += sred[w];
    float inv = 1.0f / tot;
    #pragma unroll
    for (int i = 0; i < 8; i++)
        weights[(size_t)b * S_ + tid + i * 256] = v[i] * inv;
}

// ============================================================
// K4: context partials (4-way S split) + reduce
// ============================================================
__global__ __launch_bounds__(256) void context_part_kernel(
    const float* __restrict__ keys, const float* __restrict__ weights)
{
    const int b = blockIdx.y, sc = blockIdx.z;
    const int h = blockIdx.x * 256 + threadIdx.x;
    __shared__ float sw[512];
    #pragma unroll
    for (int i = 0; i < 2; i++)
        sw[threadIdx.x + i * 256] =
            weights[(size_t)b * S_ + sc * 512 + threadIdx.x + i * 256];
    __syncthreads();

    const float* kb = keys + (size_t)b * S_ * H_ + (size_t)sc * 512 * H_ + h;
    float a0 = 0.f, a1 = 0.f, a2 = 0.f, a3 = 0.f;
    for (int s = 0; s < 512; s += 4) {
        a0 = fmaf(sw[s + 0], kb[(size_t)(s + 0) * H_], a0);
        a1 = fmaf(sw[s + 1], kb[(size_t)(s + 1) * H_], a1);
        a2 = fmaf(sw[s + 2], kb[(size_t)(s + 2) * H_], a2);
        a3 = fmaf(sw[s + 3], kb[(size_t)(s + 3) * H_], a3);
    }
    g_cpart[(size_t)sc * (B_ * H_) + (size_t)b * H_ + h] = (a0 + a1) + (a2 + a3);
}

__global__ __launch_bounds__(256) void context_reduce_kernel(float* __restrict__ ctx)
{
    int i = blockIdx.x * 256 + threadIdx.x;
    float s = 0.f;
    #pragma unroll
    for (int c = 0; c < 4; c++) s += g_cpart[(size_t)c * (B_ * H_) + i];
    ctx[i] = s;
}

// ============================================================
extern "C" void kernel_launch(void* const* d_in, const int* in_sizes, int n_in,
                              void* d_out, int out_size)
{
    const float* query = (const float*)d_in[0];
    const float* keys  = (const float*)d_in[1];
    const float* Wa_w  = (const float*)d_in[2];
    const float* Wa_b  = (const float*)d_in[3];
    const float* Ua_w  = (const float*)d_in[4];
    const float* Ua_b  = (const float*)d_in[5];
    const float* Va_w  = (const float*)d_in[6];
    // Va_b: constant shift, cancels in softmax.

    float* ctx = (float*)d_out;
    float* wts = (float*)d_out + B_ * H_;

    cudaFuncSetAttribute(score_kernel,
                         cudaFuncAttributeMaxDynamicSharedMemorySize, SMEM_SCORE);

    keys_split_kernel<<<MROWS * H_ / (256 * 4), 256>>>(keys);
    ua_prep_kernel<<<dim3(32, 32), 256>>>(Ua_w);
    qproj_kernel<<<dim3(H_ / 256, B_ / 4), 256>>>(query, Wa_w, Wa_b, Ua_b);
    score_kernel<<<dim3(4, 512), 256, SMEM_SCORE>>>(Va_w);
    softmax_kernel<<<B_, 256>>>(wts);
    context_part_kernel<<<dim3(H_ / 256, B_, 4), 256>>>(keys, wts);
    context_reduce_kernel<<<(B_ * H_) / 256, 256>>>(ctx);
}

// round 4
// speedup vs baseline: 4.1120x; 1.3596x over previous
#include <cuda_runtime.h>
#include <cuda_bf16.h>
#include <math.h>
#include <stdint.h>

#define B_ 32
#define S_ 2048
#define H_ 1024
#define D_ 2048     // H * L
#define MROWS 65536 // B*S

// ---------------- scratch (device globals; no runtime alloc) ----------------
__device__ float g_qproj[B_ * H_];                         // q@Wa + Wa_b + Ua_b
__device__ float g_qpart[8 * B_ * H_];                     // qproj k-split partials
__device__ float g_spart[4 * MROWS];                       // partial scores per 256-h block
__device__ float g_cpart[8 * B_ * H_];                     // context partials
__device__ __align__(128) __nv_bfloat16 g_keys_hi[(size_t)MROWS * H_];
__device__ __align__(128) __nv_bfloat16 g_keys_lo[(size_t)MROWS * H_];
__device__ __align__(128) __nv_bfloat16 g_UaT_hi[H_ * H_]; // Ua^T split hi [h][d]
__device__ __align__(128) __nv_bfloat16 g_UaT_lo[H_ * H_]; // Ua^T split lo [h][d]

// ---------------- PTX helpers (base PTX only) ----------------
__device__ __forceinline__ uint32_t smem_u32(const void* p) {
    uint32_t a;
    asm("{ .reg .u64 t; cvta.to.shared.u64 t, %1; cvt.u32.u64 %0, t; }" : "=r"(a) : "l"(p));
    return a;
}
__device__ __forceinline__ void cpasync16(uint32_t dst, const void* src) {
    asm volatile("cp.async.cg.shared.global [%0], [%1], 16;" :: "r"(dst), "l"(src));
}
#define CP_COMMIT() asm volatile("cp.async.commit_group;" ::: "memory")
#define CP_WAIT1()  asm volatile("cp.async.wait_group 1;" ::: "memory")

__device__ __forceinline__ void ldsm4(uint32_t (&r)[4], uint32_t a) {
    asm volatile("ldmatrix.sync.aligned.m8n8.x4.shared.b16 {%0,%1,%2,%3}, [%4];"
                 : "=r"(r[0]), "=r"(r[1]), "=r"(r[2]), "=r"(r[3]) : "r"(a));
}
__device__ __forceinline__ void mma16816(float (&d)[4], const uint32_t (&a)[4],
                                         uint32_t b0, uint32_t b1) {
    asm volatile(
        "mma.sync.aligned.m16n8k16.row.col.f32.bf16.bf16.f32 "
        "{%0,%1,%2,%3}, {%4,%5,%6,%7}, {%8,%9}, {%0,%1,%2,%3};"
        : "+f"(d[0]), "+f"(d[1]), "+f"(d[2]), "+f"(d[3])
        : "r"(a[0]), "r"(a[1]), "r"(a[2]), "r"(a[3]), "r"(b0), "r"(b1));
}

// pair-line swizzle: 64B rows, two rows per 128B line. Shift-invariant in
// steps of 16 rows (=1024 bytes), so tile steps fold into immediates.
__device__ __forceinline__ uint32_t swb(int r, int c) {
    return (uint32_t)((r >> 1) * 128 + ((((r & 1) << 2) | c) ^ ((r >> 1) & 7)) * 16);
}

__device__ __forceinline__ float tanh_fast(float x) {
    float e = __expf(-2.f * fabsf(x));
    return copysignf(__fdividef(1.f - e, 1.f + e), x);
}

// ============================================================
// P0: keys fp32 -> bf16 hi/lo split
// ============================================================
__global__ __launch_bounds__(256) void keys_split_kernel(const float* __restrict__ keys)
{
    size_t i = ((size_t)blockIdx.x * 256 + threadIdx.x) * 4;
    float4 v = *(const float4*)(keys + i);
    __nv_bfloat16 hx = __float2bfloat16(v.x), hy = __float2bfloat16(v.y);
    __nv_bfloat16 hz = __float2bfloat16(v.z), hw = __float2bfloat16(v.w);
    __nv_bfloat162 h0 = __nv_bfloat162(hx, hy), h1 = __nv_bfloat162(hz, hw);
    __nv_bfloat162 l0 = __nv_bfloat162(__float2bfloat16(v.x - __bfloat162float(hx)),
                                       __float2bfloat16(v.y - __bfloat162float(hy)));
    __nv_bfloat162 l1 = __nv_bfloat162(__float2bfloat16(v.z - __bfloat162float(hz)),
                                       __float2bfloat16(v.w - __bfloat162float(hw)));
    *(__nv_bfloat162*)(g_keys_hi + i)     = h0;
    *(__nv_bfloat162*)(g_keys_hi + i + 2) = h1;
    *(__nv_bfloat162*)(g_keys_lo + i)     = l0;
    *(__nv_bfloat162*)(g_keys_lo + i + 2) = l1;
}

// ============================================================
// P1: Ua transpose + bf16 hi/lo split
// ============================================================
__global__ __launch_bounds__(256) void ua_prep_kernel(const float* __restrict__ Ua)
{
    __shared__ float tile[32][33];
    int tx = threadIdx.x & 31, ty = threadIdx.x >> 5;
    int x0 = blockIdx.x * 32, y0 = blockIdx.y * 32;   // x: h, y: d
    #pragma unroll
    for (int j = 0; j < 4; j++)
        tile[ty + j * 8][tx] = Ua[(size_t)(y0 + ty + j * 8) * H_ + x0 + tx];
    __syncthreads();
    #pragma unroll
    for (int j = 0; j < 4; j++) {
        float v = tile[tx][ty + j * 8];
        __nv_bfloat16 hi = __float2bfloat16(v);
        __nv_bfloat16 lo = __float2bfloat16(v - __bfloat162float(hi));
        size_t o = (size_t)(x0 + ty + j * 8) * H_ + y0 + tx;
        g_UaT_hi[o] = hi;
        g_UaT_lo[o] = lo;
    }
}

// ============================================================
// K1: q projection, 8-way K-split + reduce
// ============================================================
__global__ __launch_bounds__(256) void qproj_part_kernel(
    const float* __restrict__ query, const float* __restrict__ Wa)
{
    const int h  = blockIdx.x * 256 + threadIdx.x;
    const int b  = blockIdx.y;
    const int kc = blockIdx.z;
    const float* q = query + (size_t)b * D_ + kc * 256;
    const float* w = Wa + (size_t)kc * 256 * H_ + h;
    float a = 0.f;
    #pragma unroll 8
    for (int d = 0; d < 256; d++)
        a = fmaf(q[d], w[(size_t)d * H_], a);
    g_qpart[(size_t)kc * (B_ * H_) + (size_t)b * H_ + h] = a;
}

__global__ __launch_bounds__(256) void qproj_reduce_kernel(
    const float* __restrict__ Wab, const float* __restrict__ Uab)
{
    int i = blockIdx.x * 256 + threadIdx.x;
    int h = i & (H_ - 1);
    float s = Wab[h] + Uab[h];
    #pragma unroll
    for (int c = 0; c < 8; c++) s += g_qpart[(size_t)c * (B_ * H_) + i];
    g_qproj[i] = s;
}

// ============================================================
// K2: mma.sync score kernel v2.
// 512 threads, CTA tile 128(s) x 256(h), warp tile 32x64, BK=32,
// 3-stage cp.async, single barrier/iter, hoisted addressing.
// grid (4 hblk, 512 sblk), h fastest for L2 reuse of A.
// ============================================================
#define STAGE  49152          // Ah 8K | Al 8K | Bh 16K | Bl 16K
#define OFS_AL 8192
#define OFS_BH 16384
#define SMEM_SCORE (3 * STAGE + 2048)

__global__ __launch_bounds__(512, 1) void score_kernel(const float* __restrict__ Va)
{
    extern __shared__ char smem[];
    const uint32_t sb = smem_u32(smem);
    const int tid  = threadIdx.x;
    const int wid  = tid >> 5, lane = tid & 31;
    const int wm   = wid & 3,  wn   = wid >> 2;      // 4 x 4 warp grid

    const int h0    = blockIdx.x * 256;
    const int grow0 = blockIdx.y * 128;
    const int b     = grow0 >> 11;

    float* qs = (float*)(smem + 3 * STAGE);
    float* vs = qs + 256;
    if (tid < 256) {
        qs[tid] = g_qproj[(size_t)b * H_ + h0 + tid];
        vs[tid] = Va[h0 + tid];
    }

    // ---- cp.async setup: 6 x 16B per thread per stage, bases hoisted ----
    const int cr = tid >> 2, cc = tid & 3;
    const __nv_bfloat16* srcAh = g_keys_hi + (size_t)(grow0 + cr) * H_ + cc * 8;
    const __nv_bfloat16* srcAl = g_keys_lo + (size_t)(grow0 + cr) * H_ + cc * 8;
    const __nv_bfloat16* srcBh = g_UaT_hi  + (size_t)(h0 + cr) * H_ + cc * 8;
    const __nv_bfloat16* srcBl = g_UaT_lo  + (size_t)(h0 + cr) * H_ + cc * 8;
    const uint32_t dstA = swb(cr, cc);
    const uint32_t dstB = OFS_BH + swb(cr, cc);

    #define ISSUE_STAGE(base) do {                                          \
        cpasync16((base) + dstA,                 srcAh);                    \
        cpasync16((base) + dstA + OFS_AL,        srcAl);                    \
        cpasync16((base) + dstB,                 srcBh);                    \
        cpasync16((base) + dstB + 8192,          srcBh + 128 * H_);         \
        cpasync16((base) + dstB + 16384,         srcBl);                    \
        cpasync16((base) + dstB + 24576,         srcBl + 128 * H_);         \
        srcAh += 32; srcAl += 32; srcBh += 32; srcBl += 32;                 \
    } while (0)

    // ---- ldmatrix offsets: 4 regs, tile steps are +1024B immediates ----
    const int lrow = lane & 15, lcol = lane >> 4;
    uint32_t aoff[2], boff[2];
    #pragma unroll
    for (int ks = 0; ks < 2; ks++) {
        aoff[ks] = swb(wm * 32 + lrow, ks * 2 + lcol);
        boff[ks] = OFS_BH + swb(wn * 64 + lrow, ks * 2 + lcol);
    }

    float acc[2][8][4];
    #pragma unroll
    for (int i = 0; i < 2; i++)
        #pragma unroll
        for (int j = 0; j < 8; j++)
            #pragma unroll
            for (int q = 0; q < 4; q++) acc[i][j][q] = 0.f;

    ISSUE_STAGE(sb);          CP_COMMIT();
    ISSUE_STAGE(sb + STAGE);  CP_COMMIT();

    for (int it = 0; it < 32; it++) {
        CP_WAIT1();
        __syncthreads();
        if (it < 30) ISSUE_STAGE(sb + ((it + 2) % 3) * STAGE);
        CP_COMMIT();

        const uint32_t sg = sb + (it % 3) * STAGE;
        #pragma unroll
        for (int ks = 0; ks < 2; ks++) {
            uint32_t ah[2][4], al[2][4];
            ldsm4(ah[0], sg + aoff[ks]);
            ldsm4(ah[1], sg + aoff[ks] + 1024);
            ldsm4(al[0], sg + aoff[ks] + OFS_AL);
            ldsm4(al[1], sg + aoff[ks] + OFS_AL + 1024);
            #pragma unroll
            for (int ng = 0; ng < 4; ng++) {
                uint32_t bh[4], bl[4];
                ldsm4(bh, sg + boff[ks] + ng * 1024);
                ldsm4(bl, sg + boff[ks] + ng * 1024 + 16384);
                const int nf = ng * 2;
                // split 1: Ah*Bh
                mma16816(acc[0][nf],     ah[0], bh[0], bh[2]);
                mma16816(acc[0][nf + 1], ah[0], bh[1], bh[3]);
                mma16816(acc[1][nf],     ah[1], bh[0], bh[2]);
                mma16816(acc[1][nf + 1], ah[1], bh[1], bh[3]);
                // split 2: Ah*Bl
                mma16816(acc[0][nf],     ah[0], bl[0], bl[2]);
                mma16816(acc[0][nf + 1], ah[0], bl[1], bl[3]);
                mma16816(acc[1][nf],     ah[1], bl[0], bl[2]);
                mma16816(acc[1][nf + 1], ah[1], bl[1], bl[3]);
                // split 3: Al*Bh
                mma16816(acc[0][nf],     al[0], bh[0], bh[2]);
                mma16816(acc[0][nf + 1], al[0], bh[1], bh[3]);
                mma16816(acc[1][nf],     al[1], bh[0], bh[2]);
                mma16816(acc[1][nf + 1], al[1], bh[1], bh[3]);
            }
        }
    }

    // ---- epilogue: p[row] = sum_h tanh(acc + q[h]) * Va[h] ----
    float pr[2][2] = {{0.f, 0.f}, {0.f, 0.f}};
    #pragma unroll
    for (int ms = 0; ms < 2; ms++) {
        #pragma unroll
        for (int nf = 0; nf < 8; nf++) {
            int c0 = wn * 64 + nf * 8 + (lane & 3) * 2;
            float q0v = qs[c0], q1v = qs[c0 + 1];
            float v0v = vs[c0], v1v = vs[c0 + 1];
            pr[ms][0] += tanh_fast(acc[ms][nf][0] + q0v) * v0v
                       + tanh_fast(acc[ms][nf][1] + q1v) * v1v;
            pr[ms][1] += tanh_fast(acc[ms][nf][2] + q0v) * v0v
                       + tanh_fast(acc[ms][nf][3] + q1v) * v1v;
        }
    }
    #pragma unroll
    for (int ms = 0; ms < 2; ms++)
        #pragma unroll
        for (int hf = 0; hf < 2; hf++) {
            pr[ms][hf] += __shfl_xor_sync(0xFFFFFFFFu, pr[ms][hf], 1);
            pr[ms][hf] += __shfl_xor_sync(0xFFFFFFFFu, pr[ms][hf], 2);
        }

    __syncthreads();                      // all warps done with stage smem
    float* red = (float*)smem;            // 4 x 128 floats
    if ((lane & 3) == 0) {
        #pragma unroll
        for (int ms = 0; ms < 2; ms++) {
            int row = wm * 32 + ms * 16 + (lane >> 2);
            red[wn * 128 + row]     = pr[ms][0];
            red[wn * 128 + row + 8] = pr[ms][1];
        }
    }
    __syncthreads();
    if (tid < 128)
        g_spart[(size_t)blockIdx.x * MROWS + grow0 + tid] =
            (red[tid] + red[128 + tid]) + (red[256 + tid] + red[384 + tid]);
}

// ============================================================
// K3: softmax over S per batch (4 h-block partials)
// ============================================================
__global__ __launch_bounds__(256) void softmax_kernel(float* __restrict__ weights)
{
    const int b = blockIdx.x;
    const int tid = threadIdx.x;
    const int lane = tid & 31, wid = tid >> 5;
    __shared__ float sred[8];

    float v[8];
    #pragma unroll
    for (int i = 0; i < 8; i++) {
        int s = tid + i * 256;
        float t = 0.f;
        #pragma unroll
        for (int hb = 0; hb < 4; hb++)
            t += g_spart[(size_t)hb * MROWS + (size_t)b * S_ + s];
        v[i] = t;
    }
    float m = v[0];
    #pragma unroll
    for (int i = 1; i < 8; i++) m = fmaxf(m, v[i]);
    #pragma unroll
    for (int off = 16; off > 0; off >>= 1)
        m = fmaxf(m, __shfl_xor_sync(0xFFFFFFFFu, m, off));
    if (lane == 0) sred[wid] = m;
    __syncthreads();
    float mm = sred[0];
    #pragma unroll
    for (int w = 1; w < 8; w++) mm = fmaxf(mm, sred[w]);
    __syncthreads();
    float sum = 0.f;
    #pragma unroll
    for (int i = 0; i < 8; i++) { v[i] = __expf(v[i] - mm); sum += v[i]; }
    #pragma unroll
    for (int off = 16; off > 0; off >>= 1)
        sum += __shfl_xor_sync(0xFFFFFFFFu, sum, off);
    if (lane == 0) sred[wid] = sum;
    __syncthreads();
    float tot = 0.f;
    #pragma unroll
    for (int w = 0; w < 8; w++) tot += sred[w];
    float inv = 1.0f / tot;
    #pragma unroll
    for (int i = 0; i < 8; i++)
        weights[(size_t)b * S_ + tid + i * 256] = v[i] * inv;
}

// ============================================================
// K4: context partials (8-way S split) + reduce
// ============================================================
__global__ __launch_bounds__(256) void context_part_kernel(
    const float* __restrict__ keys, const float* __restrict__ weights)
{
    const int b = blockIdx.y, sc = blockIdx.z;
    const int h = blockIdx.x * 256 + threadIdx.x;
    __shared__ float sw[256];
    sw[threadIdx.x] = weights[(size_t)b * S_ + sc * 256 + threadIdx.x];
    __syncthreads();

    const float* kb = keys + (size_t)b * S_ * H_ + (size_t)sc * 256 * H_ + h;
    float a0 = 0.f, a1 = 0.f, a2 = 0.f, a3 = 0.f;
    for (int s = 0; s < 256; s += 4) {
        a0 = fmaf(sw[s + 0], kb[(size_t)(s + 0) * H_], a0);
        a1 = fmaf(sw[s + 1], kb[(size_t)(s + 1) * H_], a1);
        a2 = fmaf(sw[s + 2], kb[(size_t)(s + 2) * H_], a2);
        a3 = fmaf(sw[s + 3], kb[(size_t)(s + 3) * H_], a3);
    }
    g_cpart[(size_t)sc * (B_ * H_) + (size_t)b * H_ + h] = (a0 + a1) + (a2 + a3);
}

__global__ __launch_bounds__(256) void context_reduce_kernel(float* __restrict__ ctx)
{
    int i = blockIdx.x * 256 + threadIdx.x;
    float s = 0.f;
    #pragma unroll
    for (int c = 0; c < 8; c++) s += g_cpart[(size_t)c * (B_ * H_) + i];
    ctx[i] = s;
}

// ============================================================
extern "C" void kernel_launch(void* const* d_in, const int* in_sizes, int n_in,
                              void* d_out, int out_size)
{
    const float* query = (const float*)d_in[0];
    const float* keys  = (const float*)d_in[1];
    const float* Wa_w  = (const float*)d_in[2];
    const float* Wa_b  = (const float*)d_in[3];
    const float* Ua_w  = (const float*)d_in[4];
    const float* Ua_b  = (const float*)d_in[5];
    const float* Va_w  = (const float*)d_in[6];
    // Va_b: constant shift of scores, cancels in softmax.

    float* ctx = (float*)d_out;
    float* wts = (float*)d_out + B_ * H_;

    cudaFuncSetAttribute(score_kernel,
                         cudaFuncAttributeMaxDynamicSharedMemorySize, SMEM_SCORE);

    keys_split_kernel<<<MROWS * H_ / (256 * 4), 256>>>(keys);
    ua_prep_kernel<<<dim3(32, 32), 256>>>(Ua_w);
    qproj_part_kernel<<<dim3(H_ / 256, B_, 8), 256>>>(query, Wa_w);
    qproj_reduce_kernel<<<(B_ * H_) / 256, 256>>>(Wa_b, Ua_b);
    score_kernel<<<dim3(4, 512), 512, SMEM_SCORE>>>(Va_w);
    softmax_kernel<<<B_, 256>>>(wts);
    context_part_kernel<<<dim3(H_ / 256, B_, 8), 256>>>(keys, wts);
    context_reduce_kernel<<<(B_ * H_) / 256, 256>>>(ctx);
}